// round 9
// baseline (speedup 1.0000x reference)
#include <cuda_runtime.h>
#include <cstdint>

// Problem constants: S=16, P=8, N=64, D=128
#define NBLK   128
#define NROW   64
#define DIMD   128
#define STRIDE 132
#define NTHR   1024

// smem: sx[64][STRIDE], sy[64][STRIDE], nx2/rnx/ny2/rny/sxs/sys[64]
#define SMEM_FLOATS (2 * NROW * STRIDE + 6 * NROW)

__global__ void __launch_bounds__(NTHR, 1)
vcmp_kernel(const float* __restrict__ X, const float* __restrict__ Y,
            float* __restrict__ out) {
    extern __shared__ float smem[];
    float* sx  = smem;
    float* sy  = smem + NROW * STRIDE;
    float* nx2 = sy + NROW * STRIDE;
    float* rnx = nx2 + NROW;
    float* ny2 = rnx + NROW;
    float* rny = ny2 + NROW;
    float* sxs = rny + NROW;   // row sums of x
    float* sys = sxs + NROW;   // row sums of y

    const int blk = blockIdx.x;
    const int t   = threadIdx.x;
    const int wid = t >> 5;
    const int lid = t & 31;

    // ---- Load x, y into padded smem (coalesced float4 global loads) ----
    const float4* xg = (const float4*)(X + (size_t)blk * NROW * DIMD);
    const float4* yg = (const float4*)(Y + (size_t)blk * NROW * DIMD);
#pragma unroll
    for (int k = 0; k < 2; k++) {
        int g    = k * NTHR + t;
        int row  = g >> 5;
        int col4 = (g & 31) * 4;
        *(float4*)(sx + row * STRIDE + col4) = xg[g];
        *(float4*)(sy + row * STRIDE + col4) = yg[g];
    }
    __syncthreads();

    // ---- Per-row norms (t<128) and row sums (t in [128,256)) ----
    if (t < 128) {
        const float* r = (t < NROW) ? (sx + t * STRIDE) : (sy + (t - NROW) * STRIDE);
        float ss = 0.f;
#pragma unroll 8
        for (int d = 0; d < DIMD; d++) ss = fmaf(r[d], r[d], ss);
        float rn = 1.0f / fmaxf(sqrtf(ss), 1e-12f);
        if (t < NROW) { nx2[t] = ss; rnx[t] = rn; }
        else          { ny2[t - NROW] = ss; rny[t - NROW] = rn; }
    } else if (t < 256) {
        const int r_ = t - 128;
        const float* r = (r_ < NROW) ? (sx + r_ * STRIDE) : (sy + (r_ - NROW) * STRIDE);
        float s = 0.f;
#pragma unroll 8
        for (int d = 0; d < DIMD; d++) s += r[d];
        if (r_ < NROW) sxs[r_] = s;
        else           sys[r_ - NROW] = s;
    }
    __syncthreads();

    // ---- Gram via mma.sync m16n8k8 tf32: C = dot(x_n, y_m) ----
    // 32 warps, each a 16x8 tile: n0=(wid>>3)*16, m0=(wid&7)*8, K=128 (16 steps)
    const int g_ = lid >> 2;
    const int tg = lid & 3;
    const int n0 = (wid >> 3) * 16;
    const int m0 = (wid & 7) * 8;

    float c0 = 0.f, c1 = 0.f, c2 = 0.f, c3 = 0.f;
    {
        const uint32_t* pa = (const uint32_t*)(sx + (n0 + g_) * STRIDE + tg);
        const uint32_t* pb = (const uint32_t*)(sy + (m0 + g_) * STRIDE + tg);
#pragma unroll
        for (int kk = 0; kk < 16; kk++) {
            const int d0 = kk * 8;
            uint32_t a0 = pa[d0];
            uint32_t a1 = pa[8 * STRIDE + d0];
            uint32_t a2 = pa[d0 + 4];
            uint32_t a3 = pa[8 * STRIDE + d0 + 4];
            uint32_t b0 = pb[d0];
            uint32_t b1 = pb[d0 + 4];
            asm volatile(
                "mma.sync.aligned.m16n8k8.row.col.f32.tf32.tf32.f32 "
                "{%0,%1,%2,%3}, {%4,%5,%6,%7}, {%8,%9}, {%0,%1,%2,%3};"
                : "+f"(c0), "+f"(c1), "+f"(c2), "+f"(c3)
                : "r"(a0), "r"(a1), "r"(a2), "r"(a3), "r"(b0), "r"(b1));
        }
    }

    // ---- L1 loop: Sum of max(x,y); FMNMX on alu pipe + FADD on fma pipe ----
    // n = 2*wid + i, m = lid + 32*j; all offsets compile-time constant
    const float* xp = sx + (wid * 2) * STRIDE;
    const float* yp = sy + lid * STRIDE;

    float am00 = 0.f, am01 = 0.f, am10 = 0.f, am11 = 0.f;

#pragma unroll 4
    for (int d = 0; d < DIMD; d += 4) {
        float4 x0 = *(const float4*)(xp + d);               // broadcast
        float4 x1 = *(const float4*)(xp + STRIDE + d);      // broadcast
        float4 y0 = *(const float4*)(yp + d);               // conflict-free
        float4 y1 = *(const float4*)(yp + 32 * STRIDE + d); // conflict-free

        am00 += fmaxf(x0.x, y0.x); am00 += fmaxf(x0.y, y0.y);
        am00 += fmaxf(x0.z, y0.z); am00 += fmaxf(x0.w, y0.w);

        am01 += fmaxf(x0.x, y1.x); am01 += fmaxf(x0.y, y1.y);
        am01 += fmaxf(x0.z, y1.z); am01 += fmaxf(x0.w, y1.w);

        am10 += fmaxf(x1.x, y0.x); am10 += fmaxf(x1.y, y0.y);
        am10 += fmaxf(x1.z, y0.z); am10 += fmaxf(x1.w, y0.w);

        am11 += fmaxf(x1.x, y1.x); am11 += fmaxf(x1.y, y1.y);
        am11 += fmaxf(x1.z, y1.z); am11 += fmaxf(x1.w, y1.w);
    }

    // ---- Stores ----
    float* oblk = out + (size_t)blk * NROW * NROW * 3;

    // L1 = 2*Sum(max) - Sx - Sy
    {
        const int n = wid * 2;
        const float s0 = sxs[n], s1 = sxs[n + 1];
        const float t0 = sys[lid], t1 = sys[lid + 32];
        oblk[(size_t)(n * NROW + lid) * 3 + 2]            = fmaf(2.0f, am00, -(s0 + t0));
        oblk[(size_t)(n * NROW + lid + 32) * 3 + 2]       = fmaf(2.0f, am01, -(s0 + t1));
        oblk[(size_t)((n + 1) * NROW + lid) * 3 + 2]      = fmaf(2.0f, am10, -(s1 + t0));
        oblk[(size_t)((n + 1) * NROW + lid + 32) * 3 + 2] = fmaf(2.0f, am11, -(s1 + t1));
    }

    // cos / l2 from MMA fragments
    {
        const int rn_[2] = {n0 + g_, n0 + g_ + 8};
        const int cm_[2] = {m0 + 2 * tg, m0 + 2 * tg + 1};
        const float cv[2][2] = {{c0, c1}, {c2, c3}};
#pragma unroll
        for (int i = 0; i < 2; i++) {
            const int n = rn_[i];
            const float xn2 = nx2[n];
            const float rxn = rnx[n];
#pragma unroll
            for (int j = 0; j < 2; j++) {
                const int m = cm_[j];
                const float dotv = cv[i][j];
                float l2v = sqrtf(fmaxf(xn2 + ny2[m] - 2.0f * dotv, 0.0f));
                float cosv = dotv * rxn * rny[m];
                float* o = oblk + (size_t)(n * NROW + m) * 3;
                o[0] = cosv;
                o[1] = l2v;
            }
        }
    }
}

extern "C" void kernel_launch(void* const* d_in, const int* in_sizes, int n_in,
                              void* d_out, int out_size) {
    const float* X = (const float*)d_in[0];
    const float* Y = (const float*)d_in[1];
    float* out = (float*)d_out;

    const int smem_bytes = SMEM_FLOATS * (int)sizeof(float);
    cudaFuncSetAttribute(vcmp_kernel, cudaFuncAttributeMaxDynamicSharedMemorySize,
                         smem_bytes);
    vcmp_kernel<<<NBLK, NTHR, smem_bytes>>>(X, Y, out);
}

// round 10
// speedup vs baseline: 1.1343x; 1.1343x over previous
#include <cuda_runtime.h>
#include <cstdint>

// Problem: S=16, P=8, N=64, D=128.  Each (s,p) block split across 2 CTAs (n-halves).
#define NBLK   128
#define NROW   64
#define NHALF  32
#define DIMD   128
#define STRIDE 132
#define NTHR   512
#define GRID   256

// smem: sx[32][STRIDE], sy[64][STRIDE] (negated y), nx2/rnx[32], ny2/rny[64]
#define SMEM_FLOATS (96 * STRIDE + 2 * NHALF + 2 * NROW)

#define ABSMASK 0x7fffffff7fffffffULL

__device__ __forceinline__ void fma2(unsigned long long& d, unsigned long long a,
                                     unsigned long long b, unsigned long long c) {
    asm("fma.rn.f32x2 %0, %1, %2, %3;" : "=l"(d) : "l"(a), "l"(b), "l"(c));
}
__device__ __forceinline__ unsigned long long add2(unsigned long long a, unsigned long long b) {
    unsigned long long d;
    asm("add.rn.f32x2 %0, %1, %2;" : "=l"(d) : "l"(a), "l"(b));
    return d;
}
__device__ __forceinline__ float lo32(unsigned long long v) {
    return __uint_as_float((unsigned)(v & 0xffffffffULL));
}
__device__ __forceinline__ float hi32(unsigned long long v) {
    return __uint_as_float((unsigned)(v >> 32));
}

// One stage: 4 pairs x one d-quad (two f32x2 halves each) — round-4 proven body
#define STEP(BX, BY)                                                          \
    _Pragma("unroll")                                                         \
    for (int i = 0; i < 2; i++) {                                             \
        _Pragma("unroll")                                                     \
        for (int j = 0; j < 2; j++) {                                         \
            unsigned long long d0 = add2(BX[i].x, BY[j].x);                   \
            unsigned long long d1 = add2(BX[i].y, BY[j].y);                   \
            fma2(ndot[i][j], BX[i].x, BY[j].x, ndot[i][j]);                   \
            fma2(ndot[i][j], BX[i].y, BY[j].y, ndot[i][j]);                   \
            l1a[i][j] = add2(l1a[i][j], d0 & ABSMASK);                        \
            l1a[i][j] = add2(l1a[i][j], d1 & ABSMASK);                        \
        }                                                                     \
    }

__global__ void __launch_bounds__(NTHR, 2)
vcmp_kernel(const float* __restrict__ X, const float* __restrict__ Y,
            float* __restrict__ out) {
    extern __shared__ float smem[];
    float* sx  = smem;                       // 32 rows
    float* sy  = smem + NHALF * STRIDE;      // 64 rows (negated)
    float* nx2 = sy + NROW * STRIDE;         // [32]
    float* rnx = nx2 + NHALF;                // [32]
    float* ny2 = rnx + NHALF;                // [64]
    float* rny = ny2 + NROW;                 // [64]

    const int blk  = blockIdx.x >> 1;        // (s,p) block
    const int half = blockIdx.x & 1;         // n-half
    const int t    = threadIdx.x;
    const int wid  = t >> 5;                 // 0..15
    const int lid  = t & 31;

    // ---- Load x-half (negged? no: keep x, negate y) + full y ----
    const float4* xg = (const float4*)(X + ((size_t)blk * NROW + half * NHALF) * DIMD);
    const float4* yg = (const float4*)(Y + (size_t)blk * NROW * DIMD);
#pragma unroll
    for (int k = 0; k < 2; k++) {            // x: 1024 float4
        int g    = k * NTHR + t;
        int row  = g >> 5;
        int col4 = (g & 31) * 4;
        *(float4*)(sx + row * STRIDE + col4) = xg[g];
    }
#pragma unroll
    for (int k = 0; k < 4; k++) {            // y: 2048 float4, negated
        int g    = k * NTHR + t;
        int row  = g >> 5;
        int col4 = (g & 31) * 4;
        float4 yv = yg[g];
        *(float4*)(sy + row * STRIDE + col4) = make_float4(-yv.x, -yv.y, -yv.z, -yv.w);
    }
    __syncthreads();

    // ---- Row norms: threads 0..95 (x: 0..31 local, y: 32..95) ----
    if (t < 96) {
        const float* r = (t < NHALF) ? (sx + t * STRIDE) : (sy + (t - NHALF) * STRIDE);
        float ss = 0.f;
#pragma unroll 8
        for (int d = 0; d < DIMD; d++) ss = fmaf(r[d], r[d], ss);
        float rn = 1.0f / fmaxf(sqrtf(ss), 1e-12f);
        if (t < NHALF) { nx2[t] = ss; rnx[t] = rn; }
        else           { ny2[t - NHALF] = ss; rny[t - NHALF] = rn; }
    }
    __syncthreads();

    // ---- Main loop: 2x2 pair tile, LDS.128, 2-stage pipeline (round-4 body) ----
    // n_local = 2*wid + i (wid 0..15 -> covers 32 rows), m = lid + 32*j
    const float* xp0 = sx + (wid * 2) * STRIDE;
    const float* yp0 = sy + lid * STRIDE;

    unsigned long long ndot[2][2];  // accumulates x*(-y) -> -dot
    unsigned long long l1a[2][2];   // accumulates |x-y|
#pragma unroll
    for (int i = 0; i < 2; i++)
#pragma unroll
        for (int j = 0; j < 2; j++) { ndot[i][j] = 0ULL; l1a[i][j] = 0ULL; }

    ulonglong2 ax[2], ay[2], bx[2], by[2];
#pragma unroll
    for (int i = 0; i < 2; i++) ax[i] = *(const ulonglong2*)(xp0 + i * STRIDE);
#pragma unroll
    for (int j = 0; j < 2; j++) ay[j] = *(const ulonglong2*)(yp0 + j * 32 * STRIDE);

#pragma unroll 2
    for (int d = 0; d < DIMD; d += 8) {
#pragma unroll
        for (int i = 0; i < 2; i++) bx[i] = *(const ulonglong2*)(xp0 + i * STRIDE + d + 4);
#pragma unroll
        for (int j = 0; j < 2; j++) by[j] = *(const ulonglong2*)(yp0 + j * 32 * STRIDE + d + 4);
        STEP(ax, ay)
        // d=120 prefetch reads pad cols 128..131: in-bounds, unused
#pragma unroll
        for (int i = 0; i < 2; i++) ax[i] = *(const ulonglong2*)(xp0 + i * STRIDE + d + 8);
#pragma unroll
        for (int j = 0; j < 2; j++) ay[j] = *(const ulonglong2*)(yp0 + j * 32 * STRIDE + d + 8);
        STEP(bx, by)
    }

    // ---- Epilogue: cos / l2 / l1 per pair ----
    float* oblk = out + (size_t)blk * NROW * NROW * 3;
#pragma unroll
    for (int i = 0; i < 2; i++) {
        const int nl = wid * 2 + i;            // local n (0..31)
        const int n  = half * NHALF + nl;      // global n
        const float xn2 = nx2[nl];
        const float rxn = rnx[nl];
#pragma unroll
        for (int j = 0; j < 2; j++) {
            const int m = lid + 32 * j;
            unsigned long long nd = ndot[i][j];
            float dotv = -(lo32(nd) + hi32(nd));
            unsigned long long la = l1a[i][j];
            float l1v = lo32(la) + hi32(la);
            float l2v = sqrtf(fmaxf(xn2 + ny2[m] - 2.0f * dotv, 0.0f));
            float cosv = dotv * rxn * rny[m];
            float* o = oblk + (size_t)(n * NROW + m) * 3;
            o[0] = cosv; o[1] = l2v; o[2] = l1v;
        }
    }
}

extern "C" void kernel_launch(void* const* d_in, const int* in_sizes, int n_in,
                              void* d_out, int out_size) {
    const float* X = (const float*)d_in[0];
    const float* Y = (const float*)d_in[1];
    float* out = (float*)d_out;

    const int smem_bytes = SMEM_FLOATS * (int)sizeof(float);   // 51,456 B
    cudaFuncSetAttribute(vcmp_kernel, cudaFuncAttributeMaxDynamicSharedMemorySize,
                         smem_bytes);
    vcmp_kernel<<<GRID, NTHR, smem_bytes>>>(X, Y, out);
}